// round 11
// baseline (speedup 1.0000x reference)
#include <cuda_runtime.h>
#include <cstdint>

// ---------------------------------------------------------------------------
// Problem constants
// ---------------------------------------------------------------------------
#define T_  2048
#define B_  256
#define I_  64
#define H_  128
#define G4_ 512   // 4*H
#define NH_ 512
#define O_  64

// Device-global scratch (allocation-free rule)
__device__ float g_xg[(size_t)T_ * B_ * G4_];   // [T,B,4H]
__device__ float g_hs[(size_t)T_ * B_ * H_];    // [T,B,H]
__device__ float g_Wxh[I_ * G4_];               // [k=64][g=512] tf32 hi (transposed W_ih)
__device__ float g_Wxl[I_ * G4_];
__device__ float g_W1h[H_ * NH_];               // [k=128][nh=512] tf32 hi (transposed W1)
__device__ float g_W1l[H_ * NH_];
__device__ float g_W2h[NH_ * O_];               // [nh=512][o=64]  tf32 hi (transposed W2)
__device__ float g_W2l[NH_ * O_];

// Output layout: out[T,B,O] | hT[1,B,H] | cT[1,B,H]
#define OUT_ELEMS ((size_t)T_ * B_ * O_)
#define HT_OFF    (OUT_ELEMS)
#define CT_OFF    (OUT_ELEMS + (size_t)B_ * H_)

__device__ __forceinline__ float sigf(float x)      { return 1.f / (1.f + __expf(-x)); }
__device__ __forceinline__ float tanhfast(float x)  { return 2.f / (1.f + __expf(-2.f * x)) - 1.f; }

// ---------------------------------------------------------------------------
// tf32 helpers (mma.sync works on base sm_103; tcgen05 does not — harness
// emits compute_103 PTX without the 'a' suffix)
// ---------------------------------------------------------------------------
__device__ __forceinline__ void tf32_split(float a, uint32_t& hi, uint32_t& lo) {
    uint32_t h;
    asm("cvt.rna.tf32.f32 %0, %1;" : "=r"(h) : "f"(a));
    float r = a - __uint_as_float(h);
    uint32_t l;
    asm("cvt.rna.tf32.f32 %0, %1;" : "=r"(l) : "f"(r));
    hi = h; lo = l;
}

__device__ __forceinline__ void mma8(float* d, const uint32_t* a, const uint32_t* b) {
    asm volatile("mma.sync.aligned.m16n8k8.row.col.f32.tf32.tf32.f32 "
                 "{%0,%1,%2,%3}, {%4,%5,%6,%7}, {%8,%9}, {%0,%1,%2,%3};"
                 : "+f"(d[0]), "+f"(d[1]), "+f"(d[2]), "+f"(d[3])
                 : "r"(a[0]), "r"(a[1]), "r"(a[2]), "r"(a[3]), "r"(b[0]), "r"(b[1]));
}

// ---------------------------------------------------------------------------
// Kernel P: pre-split weights into tf32 hi/lo planes (transposed for col-major B)
// ---------------------------------------------------------------------------
__global__ void prep_kernel(const float* __restrict__ Wih,
                            const float* __restrict__ W1,
                            const float* __restrict__ W2) {
    int i0 = blockIdx.x * blockDim.x + threadIdx.x;
    int st = gridDim.x * blockDim.x;
    for (int i = i0; i < G4_ * I_; i += st) {        // W_ih [g][k] -> [k][g]
        int g = i >> 6, k = i & 63;
        uint32_t h, l;
        tf32_split(Wih[i], h, l);
        g_Wxh[k * G4_ + g] = __uint_as_float(h);
        g_Wxl[k * G4_ + g] = __uint_as_float(l);
    }
    for (int i = i0; i < NH_ * H_; i += st) {        // W1 [nh][k] -> [k][nh]
        int nh = i >> 7, k = i & 127;
        uint32_t h, l;
        tf32_split(W1[i], h, l);
        g_W1h[k * NH_ + nh] = __uint_as_float(h);
        g_W1l[k * NH_ + nh] = __uint_as_float(l);
    }
    for (int i = i0; i < O_ * NH_; i += st) {        // W2 [o][nh] -> [nh][o]
        int o = i >> 9, nh = i & 511;
        uint32_t h, l;
        tf32_split(W2[i], h, l);
        g_W2h[nh * O_ + o] = __uint_as_float(h);
        g_W2l[nh * O_ + o] = __uint_as_float(l);
    }
}

// ---------------------------------------------------------------------------
// Kernel A (mma): xg[row,g] = x @ W_ih^T + bias.  (unchanged from R10)
// ---------------------------------------------------------------------------
#define XAh_ 0
#define XAl_ (XAh_ + 128 * 68)    // 8704
#define XBh_ (XAl_ + 128 * 68)    // 17408
#define XBl_ (XBh_ +  64 * 72)    // 22016
#define XBI_ (XBl_ +  64 * 72)    // 26624
#define XG_SMEM_BYTES ((XBI_ + 512) * 4)   // 108544

__global__ void __launch_bounds__(256, 2) xg_mma_kernel(const float* __restrict__ x,
                                                        const float* __restrict__ bih,
                                                        const float* __restrict__ bhh) {
    extern __shared__ float sm[];
    const int tid = threadIdx.x;
    const int lane = tid & 31;
    const int w = tid >> 5;
    const int mg = w & 3;
    const int nh2 = w >> 2;
    const size_t rowBase = (size_t)blockIdx.x * 128;

    const int rA = mg * 32 + (lane >> 2);
    const int kA = lane & 3;
    const int cB = lane >> 2;
    const int kB = lane & 3;

    for (int i = tid; i < 2048; i += 256) {
        int r = i >> 4, c4 = i & 15;
        float4 v = reinterpret_cast<const float4*>(x)[(rowBase + r) * 16 + c4];
        uint32_t h, l;
        float* dh = &sm[XAh_ + r * 68 + c4 * 4];
        float* dl = &sm[XAl_ + r * 68 + c4 * 4];
        tf32_split(v.x, h, l); dh[0] = __uint_as_float(h); dl[0] = __uint_as_float(l);
        tf32_split(v.y, h, l); dh[1] = __uint_as_float(h); dl[1] = __uint_as_float(l);
        tf32_split(v.z, h, l); dh[2] = __uint_as_float(h); dl[2] = __uint_as_float(l);
        tf32_split(v.w, h, l); dh[3] = __uint_as_float(h); dl[3] = __uint_as_float(l);
    }
    for (int i = tid; i < G4_; i += 256) sm[XBI_ + i] = bih[i] + bhh[i];

    for (int ch = 0; ch < 8; ch++) {
        __syncthreads();
        for (int i = tid; i < 1024; i += 256) {
            int k = i >> 4, n4 = i & 15;
            *reinterpret_cast<float4*>(&sm[XBh_ + k * 72 + n4 * 4]) =
                reinterpret_cast<const float4*>(g_Wxh)[k * 128 + ch * 16 + n4];
            *reinterpret_cast<float4*>(&sm[XBl_ + k * 72 + n4 * 4]) =
                reinterpret_cast<const float4*>(g_Wxl)[k * 128 + ch * 16 + n4];
        }
        __syncthreads();

        float acc[2][4][4];
#pragma unroll
        for (int mf = 0; mf < 2; mf++)
#pragma unroll
            for (int nt = 0; nt < 4; nt++)
#pragma unroll
                for (int q = 0; q < 4; q++) acc[mf][nt][q] = 0.f;

#pragma unroll
        for (int ks = 0; ks < 8; ks++) {
            uint32_t Ah[2][4], Al[2][4];
#pragma unroll
            for (int mf = 0; mf < 2; mf++) {
                int r = rA + mf * 16;
                int k = ks * 8 + kA;
                Ah[mf][0] = __float_as_uint(sm[XAh_ + r * 68 + k]);
                Ah[mf][1] = __float_as_uint(sm[XAh_ + (r + 8) * 68 + k]);
                Ah[mf][2] = __float_as_uint(sm[XAh_ + r * 68 + k + 4]);
                Ah[mf][3] = __float_as_uint(sm[XAh_ + (r + 8) * 68 + k + 4]);
                Al[mf][0] = __float_as_uint(sm[XAl_ + r * 68 + k]);
                Al[mf][1] = __float_as_uint(sm[XAl_ + (r + 8) * 68 + k]);
                Al[mf][2] = __float_as_uint(sm[XAl_ + r * 68 + k + 4]);
                Al[mf][3] = __float_as_uint(sm[XAl_ + (r + 8) * 68 + k + 4]);
            }
#pragma unroll
            for (int nt = 0; nt < 4; nt++) {
                int n = nh2 * 32 + nt * 8 + cB;
                int k = ks * 8 + kB;
                uint32_t Bh[2], Bl[2];
                Bh[0] = __float_as_uint(sm[XBh_ + k * 72 + n]);
                Bh[1] = __float_as_uint(sm[XBh_ + (k + 4) * 72 + n]);
                Bl[0] = __float_as_uint(sm[XBl_ + k * 72 + n]);
                Bl[1] = __float_as_uint(sm[XBl_ + (k + 4) * 72 + n]);
#pragma unroll
                for (int mf = 0; mf < 2; mf++) {
                    mma8(acc[mf][nt], Ah[mf], Bh);
                    mma8(acc[mf][nt], Al[mf], Bh);
                    mma8(acc[mf][nt], Ah[mf], Bl);
                }
            }
        }

#pragma unroll
        for (int mf = 0; mf < 2; mf++) {
            size_t r0 = rowBase + rA + mf * 16;
#pragma unroll
            for (int nt = 0; nt < 4; nt++) {
                int col = ch * 64 + nh2 * 32 + nt * 8 + (lane & 3) * 2;
                float bb0 = sm[XBI_ + col];
                float bb1 = sm[XBI_ + col + 1];
                float2 v0, v1;
                v0.x = acc[mf][nt][0] + bb0;
                v0.y = acc[mf][nt][1] + bb1;
                v1.x = acc[mf][nt][2] + bb0;
                v1.y = acc[mf][nt][3] + bb1;
                *reinterpret_cast<float2*>(&g_xg[r0 * G4_ + col]) = v0;
                *reinterpret_cast<float2*>(&g_xg[(r0 + 8) * G4_ + col]) = v1;
            }
        }
    }
}

// ---------------------------------------------------------------------------
// Kernel B: persistent LSTM scan — RESTRUCTURED.
// 128 CTAs x 128 threads (1 warp/SMSP).  Thread u owns unit u: computes all
// 4 gates (i,f,g,o) for BOTH batch rows -> cell update is thread-local ->
// NO gate exchange, ONE __syncthreads per step (sH double-buffered).
// W_hh: k<108 in SMEM (221 KB, stride 27 f4 odd => conflict-free), k>=108 in
// regs (4 gates x 20 = 80 regs).  Weight rows each read by exactly 1 thread.
// ---------------------------------------------------------------------------
#define KS_ 108
#define KR_ 20
#define LSTM_SMEM_BYTES ((G4_ * KS_ + 2 * 2 * H_) * 4)   // 221184 + 2048 = 223232

__global__ void __launch_bounds__(128, 1) lstm_kernel(const float* __restrict__ Whh,
                                                      float* __restrict__ outp) {
    extern __shared__ float smem[];
    float* sW = smem;                 // [512 gate-rows][108]
    float* sH = sW + G4_ * KS_;       // 2 buffers x [2 rows][128]

    const int u = threadIdx.x;        // unit 0..127
    const int row0 = blockIdx.x * 2;

    // stage W_hh k<108 (27 float4 per gate row; gmem row stride = 32 float4)
    const float4* W4 = reinterpret_cast<const float4*>(Whh);
    float4* sW4 = reinterpret_cast<float4*>(sW);
    for (int idx = u; idx < G4_ * 27; idx += 128) {
        int g = idx / 27, k4 = idx % 27;
        sW4[g * 27 + k4] = W4[g * 32 + k4];
    }
    // register tail weights k = 108..127, 4 gate rows for this unit
    float rw[4][KR_];
#pragma unroll
    for (int g = 0; g < 4; g++)
#pragma unroll
        for (int j = 0; j < KR_; j++)
            rw[g][j] = Whh[(g * H_ + u) * H_ + KS_ + j];

    sH[u] = 0.f; sH[H_ + u] = 0.f;    // buffer 0 = initial h
    float c0 = 0.f, c1 = 0.f;
    float h0v = 0.f, h1v = 0.f;
    __syncthreads();

    const float4* wp0 = sW4 + (0 * H_ + u) * 27;
    const float4* wp1 = sW4 + (1 * H_ + u) * 27;
    const float4* wp2 = sW4 + (2 * H_ + u) * 27;
    const float4* wp3 = sW4 + (3 * H_ + u) * 27;

    // prefetch xg for t=0: xn[g][b]
    float xn[4][2];
    {
        size_t pb = (size_t)row0 * G4_;
#pragma unroll
        for (int g = 0; g < 4; g++) {
            xn[g][0] = g_xg[pb + g * H_ + u];
            xn[g][1] = g_xg[pb + G4_ + g * H_ + u];
        }
    }

    for (int t = 0; t < T_; t++) {
        const int p = t & 1;
        const float4* h0p = reinterpret_cast<const float4*>(sH + p * 2 * H_);
        const float4* h1p = reinterpret_cast<const float4*>(sH + p * 2 * H_ + H_);

        float a[4][2];
#pragma unroll
        for (int g = 0; g < 4; g++) { a[g][0] = xn[g][0]; a[g][1] = xn[g][1]; }

        if (t + 1 < T_) {   // prefetch next timestep (consumed next iteration)
            size_t nb = ((size_t)(t + 1) * B_ + row0) * G4_;
#pragma unroll
            for (int g = 0; g < 4; g++) {
                xn[g][0] = g_xg[nb + g * H_ + u];
                xn[g][1] = g_xg[nb + G4_ + g * H_ + u];
            }
        }

#pragma unroll 9
        for (int k4 = 0; k4 < 27; k4++) {
            float4 h0 = h0p[k4], h1 = h1p[k4];
            float4 w0 = wp0[k4], w1 = wp1[k4], w2 = wp2[k4], w3 = wp3[k4];
            a[0][0] += w0.x*h0.x + w0.y*h0.y + w0.z*h0.z + w0.w*h0.w;
            a[0][1] += w0.x*h1.x + w0.y*h1.y + w0.z*h1.z + w0.w*h1.w;
            a[1][0] += w1.x*h0.x + w1.y*h0.y + w1.z*h0.z + w1.w*h0.w;
            a[1][1] += w1.x*h1.x + w1.y*h1.y + w1.z*h1.z + w1.w*h1.w;
            a[2][0] += w2.x*h0.x + w2.y*h0.y + w2.z*h0.z + w2.w*h0.w;
            a[2][1] += w2.x*h1.x + w2.y*h1.y + w2.z*h1.z + w2.w*h1.w;
            a[3][0] += w3.x*h0.x + w3.y*h0.y + w3.z*h0.z + w3.w*h0.w;
            a[3][1] += w3.x*h1.x + w3.y*h1.y + w3.z*h1.z + w3.w*h1.w;
        }
#pragma unroll
        for (int j4 = 0; j4 < 5; j4++) {   // register tail k = 108..127
            float4 h0 = h0p[27 + j4], h1 = h1p[27 + j4];
#pragma unroll
            for (int g = 0; g < 4; g++) {
                a[g][0] += rw[g][4*j4]*h0.x + rw[g][4*j4+1]*h0.y + rw[g][4*j4+2]*h0.z + rw[g][4*j4+3]*h0.w;
                a[g][1] += rw[g][4*j4]*h1.x + rw[g][4*j4+1]*h1.y + rw[g][4*j4+2]*h1.z + rw[g][4*j4+3]*h1.w;
            }
        }

        // thread-local LSTM cell update (PyTorch gate order i,f,g,o)
        {
            float iv = sigf(a[0][0]), fv = sigf(a[1][0]);
            float gv = tanhfast(a[2][0]), ov = sigf(a[3][0]);
            c0 = fv * c0 + iv * gv;
            h0v = ov * tanhfast(c0);
        }
        {
            float iv = sigf(a[0][1]), fv = sigf(a[1][1]);
            float gv = tanhfast(a[2][1]), ov = sigf(a[3][1]);
            c1 = fv * c1 + iv * gv;
            h1v = ov * tanhfast(c1);
        }
        float* sHn = sH + (p ^ 1) * 2 * H_;
        sHn[u] = h0v;
        sHn[H_ + u] = h1v;
        g_hs[((size_t)t * B_ + row0) * H_ + u] = h0v;
        g_hs[((size_t)t * B_ + row0 + 1) * H_ + u] = h1v;
        __syncthreads();   // the ONLY per-step barrier
    }
    outp[HT_OFF + (size_t)row0 * H_ + u] = h0v;
    outp[HT_OFF + (size_t)(row0 + 1) * H_ + u] = h1v;
    outp[CT_OFF + (size_t)row0 * H_ + u] = c0;
    outp[CT_OFF + (size_t)(row0 + 1) * H_ + u] = c1;
}

// ---------------------------------------------------------------------------
// Kernel C (mma): fused MLP — R10/R8 version (proven 2.05 ms), unchanged.
// ---------------------------------------------------------------------------
#define SA_    0
#define SB1H_  (SA_   + 128 * 132)       // 16896
#define SB1L_  (SB1H_ + 128 * 72)        // 26112
#define SHID_  (SB1L_ + 128 * 72)        // 35328
#define SW2H_  (SHID_ + 128 * 68)        // 44032
#define SW2L_  (SW2H_ +  64 * 72)        // 48640
#define SB1V_  (SW2L_ +  64 * 72)        // 53248
#define SB2V_  (SB1V_ + 512)             // 53760
#define MLP_SMEM_BYTES  ((SB2V_ + 64) * 4)   // 215296

__global__ void __launch_bounds__(256, 1) mlp_mma_kernel(const float* __restrict__ b1,
                                                         const float* __restrict__ b2,
                                                         float* __restrict__ outp) {
    extern __shared__ float sm[];
    const int tid = threadIdx.x;
    const int lane = tid & 31;
    const int w = tid >> 5;
    const int mg = w & 3;
    const int nh2 = w >> 2;
    const size_t rowBase = (size_t)blockIdx.x * 128;

    const int rA = mg * 32 + (lane >> 2);
    const int kA = lane & 3;
    const int cB = lane >> 2;
    const int kB = lane & 3;

    for (int i = tid; i < 4096; i += 256) {
        int r = i >> 5, c4 = i & 31;
        float4 v = reinterpret_cast<const float4*>(g_hs)[(rowBase + r) * 32 + c4];
        *reinterpret_cast<float4*>(&sm[SA_ + r * 132 + c4 * 4]) = v;
    }
    for (int i = tid; i < NH_; i += 256) sm[SB1V_ + i] = b1[i];
    if (tid < O_) sm[SB2V_ + tid] = b2[tid];

    float accO[2][4][4];
#pragma unroll
    for (int mf = 0; mf < 2; mf++)
#pragma unroll
        for (int nt = 0; nt < 4; nt++)
#pragma unroll
            for (int q = 0; q < 4; q++) accO[mf][nt][q] = 0.f;

    for (int c = 0; c < 8; c++) {
        __syncthreads();
        for (int i = tid; i < 2048; i += 256) {
            int k = i >> 4, n4 = i & 15;
            *reinterpret_cast<float4*>(&sm[SB1H_ + k * 72 + n4 * 4]) =
                reinterpret_cast<const float4*>(g_W1h)[k * 128 + c * 16 + n4];
            *reinterpret_cast<float4*>(&sm[SB1L_ + k * 72 + n4 * 4]) =
                reinterpret_cast<const float4*>(g_W1l)[k * 128 + c * 16 + n4];
        }
        for (int i = tid; i < 1024; i += 256) {
            int k = i >> 4, n4 = i & 15;
            *reinterpret_cast<float4*>(&sm[SW2H_ + k * 72 + n4 * 4]) =
                reinterpret_cast<const float4*>(g_W2h)[(c * 64 + k) * 16 + n4];
            *reinterpret_cast<float4*>(&sm[SW2L_ + k * 72 + n4 * 4]) =
                reinterpret_cast<const float4*>(g_W2l)[(c * 64 + k) * 16 + n4];
        }
        __syncthreads();

        float acc[2][4][4];
#pragma unroll
        for (int mf = 0; mf < 2; mf++)
#pragma unroll
            for (int nt = 0; nt < 4; nt++)
#pragma unroll
                for (int q = 0; q < 4; q++) acc[mf][nt][q] = 0.f;

#pragma unroll 2
        for (int ks = 0; ks < 16; ks++) {
            uint32_t Ah[2][4], Al[2][4];
#pragma unroll
            for (int mf = 0; mf < 2; mf++) {
                int r = rA + mf * 16;
                int k = ks * 8 + kA;
                float a0 = sm[SA_ + r * 132 + k];
                float a1 = sm[SA_ + (r + 8) * 132 + k];
                float a2 = sm[SA_ + r * 132 + k + 4];
                float a3 = sm[SA_ + (r + 8) * 132 + k + 4];
                tf32_split(a0, Ah[mf][0], Al[mf][0]);
                tf32_split(a1, Ah[mf][1], Al[mf][1]);
                tf32_split(a2, Ah[mf][2], Al[mf][2]);
                tf32_split(a3, Ah[mf][3], Al[mf][3]);
            }
#pragma unroll
            for (int nt = 0; nt < 4; nt++) {
                int n = nh2 * 32 + nt * 8 + cB;
                int k = ks * 8 + kB;
                uint32_t Bh[2], Bl[2];
                Bh[0] = __float_as_uint(sm[SB1H_ + k * 72 + n]);
                Bh[1] = __float_as_uint(sm[SB1H_ + (k + 4) * 72 + n]);
                Bl[0] = __float_as_uint(sm[SB1L_ + k * 72 + n]);
                Bl[1] = __float_as_uint(sm[SB1L_ + (k + 4) * 72 + n]);
#pragma unroll
                for (int mf = 0; mf < 2; mf++) {
                    mma8(acc[mf][nt], Ah[mf], Bh);
                    mma8(acc[mf][nt], Ah[mf], Bl);
                    mma8(acc[mf][nt], Al[mf], Bh);
                }
            }
        }

#pragma unroll
        for (int mf = 0; mf < 2; mf++)
#pragma unroll
            for (int nt = 0; nt < 4; nt++) {
                int r = rA + mf * 16;
                int col = nh2 * 32 + nt * 8 + (lane & 3) * 2;
                float bb0 = sm[SB1V_ + c * 64 + col];
                float bb1 = sm[SB1V_ + c * 64 + col + 1];
                float2 v0, v1;
                v0.x = fmaxf(acc[mf][nt][0] + bb0, 0.f);
                v0.y = fmaxf(acc[mf][nt][1] + bb1, 0.f);
                v1.x = fmaxf(acc[mf][nt][2] + bb0, 0.f);
                v1.y = fmaxf(acc[mf][nt][3] + bb1, 0.f);
                *reinterpret_cast<float2*>(&sm[SHID_ + r * 68 + col]) = v0;
                *reinterpret_cast<float2*>(&sm[SHID_ + (r + 8) * 68 + col]) = v1;
            }
        __syncthreads();

#pragma unroll 2
        for (int ks = 0; ks < 8; ks++) {
            uint32_t Ah[2][4], Al[2][4];
#pragma unroll
            for (int mf = 0; mf < 2; mf++) {
                int r = rA + mf * 16;
                int k = ks * 8 + kA;
                float a0 = sm[SHID_ + r * 68 + k];
                float a1 = sm[SHID_ + (r + 8) * 68 + k];
                float a2 = sm[SHID_ + r * 68 + k + 4];
                float a3 = sm[SHID_ + (r + 8) * 68 + k + 4];
                tf32_split(a0, Ah[mf][0], Al[mf][0]);
                tf32_split(a1, Ah[mf][1], Al[mf][1]);
                tf32_split(a2, Ah[mf][2], Al[mf][2]);
                tf32_split(a3, Ah[mf][3], Al[mf][3]);
            }
#pragma unroll
            for (int nt = 0; nt < 4; nt++) {
                int n = nh2 * 32 + nt * 8 + cB;
                int k = ks * 8 + kB;
                uint32_t Bh[2], Bl[2];
                Bh[0] = __float_as_uint(sm[SW2H_ + k * 72 + n]);
                Bh[1] = __float_as_uint(sm[SW2H_ + (k + 4) * 72 + n]);
                Bl[0] = __float_as_uint(sm[SW2L_ + k * 72 + n]);
                Bl[1] = __float_as_uint(sm[SW2L_ + (k + 4) * 72 + n]);
#pragma unroll
                for (int mf = 0; mf < 2; mf++) {
                    mma8(accO[mf][nt], Ah[mf], Bh);
                    mma8(accO[mf][nt], Ah[mf], Bl);
                    mma8(accO[mf][nt], Al[mf], Bh);
                }
            }
        }
    }

#pragma unroll
    for (int mf = 0; mf < 2; mf++) {
        size_t r0 = rowBase + rA + mf * 16;
#pragma unroll
        for (int nt = 0; nt < 4; nt++) {
            int col = nh2 * 32 + nt * 8 + (lane & 3) * 2;
            float bo0 = sm[SB2V_ + col];
            float bo1 = sm[SB2V_ + col + 1];
            float2 v0, v1;
            v0.x = accO[mf][nt][0] + bo0;
            v0.y = accO[mf][nt][1] + bo1;
            v1.x = accO[mf][nt][2] + bo0;
            v1.y = accO[mf][nt][3] + bo1;
            *reinterpret_cast<float2*>(outp + r0 * O_ + col) = v0;
            *reinterpret_cast<float2*>(outp + (r0 + 8) * O_ + col) = v1;
        }
    }
}

// ---------------------------------------------------------------------------
// Launcher
// ---------------------------------------------------------------------------
extern "C" void kernel_launch(void* const* d_in, const int* in_sizes, int n_in,
                              void* d_out, int out_size) {
    const float* x    = (const float*)d_in[0];
    const float* Wih  = (const float*)d_in[1];
    const float* Whh  = (const float*)d_in[2];
    const float* bih  = (const float*)d_in[3];
    const float* bhh  = (const float*)d_in[4];
    const float* W1   = (const float*)d_in[5];
    const float* b1   = (const float*)d_in[6];
    const float* W2   = (const float*)d_in[7];
    const float* b2   = (const float*)d_in[8];
    float* out = (float*)d_out;

    cudaFuncSetAttribute(xg_mma_kernel,  cudaFuncAttributeMaxDynamicSharedMemorySize, XG_SMEM_BYTES);
    cudaFuncSetAttribute(lstm_kernel,    cudaFuncAttributeMaxDynamicSharedMemorySize, LSTM_SMEM_BYTES);
    cudaFuncSetAttribute(mlp_mma_kernel, cudaFuncAttributeMaxDynamicSharedMemorySize, MLP_SMEM_BYTES);

    prep_kernel<<<64, 256>>>(Wih, W1, W2);
    xg_mma_kernel<<<(T_ * B_) / 128, 256, XG_SMEM_BYTES>>>(x, bih, bhh);
    lstm_kernel<<<B_ / 2, 128, LSTM_SMEM_BYTES>>>(Whh, out);
    mlp_mma_kernel<<<(T_ * B_) / 128, 256, MLP_SMEM_BYTES>>>(b1, b2, out);
}

// round 12
// speedup vs baseline: 1.6513x; 1.6513x over previous
#include <cuda_runtime.h>
#include <cstdint>

// ---------------------------------------------------------------------------
// Problem constants
// ---------------------------------------------------------------------------
#define T_  2048
#define B_  256
#define I_  64
#define H_  128
#define G4_ 512   // 4*H
#define NH_ 512
#define O_  64

// Device-global scratch (allocation-free rule)
__device__ float g_xg[(size_t)T_ * B_ * G4_];   // [T,B,4H]
__device__ float g_hs[(size_t)T_ * B_ * H_];    // [T,B,H]
__device__ float g_Wxh[I_ * G4_];               // [k=64][g=512] tf32 hi (transposed W_ih)
__device__ float g_Wxl[I_ * G4_];
__device__ float g_W1h[H_ * NH_];               // [k=128][nh=512] tf32 hi (transposed W1)
__device__ float g_W1l[H_ * NH_];
__device__ float g_W2h[NH_ * O_];               // [nh=512][o=64]  tf32 hi (transposed W2)
__device__ float g_W2l[NH_ * O_];

// Output layout: out[T,B,O] | hT[1,B,H] | cT[1,B,H]
#define OUT_ELEMS ((size_t)T_ * B_ * O_)
#define HT_OFF    (OUT_ELEMS)
#define CT_OFF    (OUT_ELEMS + (size_t)B_ * H_)

__device__ __forceinline__ float sigf(float x)      { return 1.f / (1.f + __expf(-x)); }
__device__ __forceinline__ float tanhfast(float x)  { return 2.f / (1.f + __expf(-2.f * x)) - 1.f; }

// ---------------------------------------------------------------------------
// tf32 helpers (mma.sync works on base sm_103; tcgen05 does not — harness
// emits compute_103 PTX without the 'a' suffix)
// ---------------------------------------------------------------------------
__device__ __forceinline__ void tf32_split(float a, uint32_t& hi, uint32_t& lo) {
    uint32_t h;
    asm("cvt.rna.tf32.f32 %0, %1;" : "=r"(h) : "f"(a));
    float r = a - __uint_as_float(h);
    uint32_t l;
    asm("cvt.rna.tf32.f32 %0, %1;" : "=r"(l) : "f"(r));
    hi = h; lo = l;
}

__device__ __forceinline__ void mma8(float* d, const uint32_t* a, const uint32_t* b) {
    asm volatile("mma.sync.aligned.m16n8k8.row.col.f32.tf32.tf32.f32 "
                 "{%0,%1,%2,%3}, {%4,%5,%6,%7}, {%8,%9}, {%0,%1,%2,%3};"
                 : "+f"(d[0]), "+f"(d[1]), "+f"(d[2]), "+f"(d[3])
                 : "r"(a[0]), "r"(a[1]), "r"(a[2]), "r"(a[3]), "r"(b[0]), "r"(b[1]));
}

// ---------------------------------------------------------------------------
// Kernel P: pre-split weights into tf32 hi/lo planes (transposed for col-major B)
// ---------------------------------------------------------------------------
__global__ void prep_kernel(const float* __restrict__ Wih,
                            const float* __restrict__ W1,
                            const float* __restrict__ W2) {
    int i0 = blockIdx.x * blockDim.x + threadIdx.x;
    int st = gridDim.x * blockDim.x;
    for (int i = i0; i < G4_ * I_; i += st) {        // W_ih [g][k] -> [k][g]
        int g = i >> 6, k = i & 63;
        uint32_t h, l;
        tf32_split(Wih[i], h, l);
        g_Wxh[k * G4_ + g] = __uint_as_float(h);
        g_Wxl[k * G4_ + g] = __uint_as_float(l);
    }
    for (int i = i0; i < NH_ * H_; i += st) {        // W1 [nh][k] -> [k][nh]
        int nh = i >> 7, k = i & 127;
        uint32_t h, l;
        tf32_split(W1[i], h, l);
        g_W1h[k * NH_ + nh] = __uint_as_float(h);
        g_W1l[k * NH_ + nh] = __uint_as_float(l);
    }
    for (int i = i0; i < O_ * NH_; i += st) {        // W2 [o][nh] -> [nh][o]
        int o = i >> 9, nh = i & 511;
        uint32_t h, l;
        tf32_split(W2[i], h, l);
        g_W2h[nh * O_ + o] = __uint_as_float(h);
        g_W2l[nh * O_ + o] = __uint_as_float(l);
    }
}

// ---------------------------------------------------------------------------
// Kernel A (mma): xg[row,g] = x @ W_ih^T + bias.  (byte-identical to R10)
// ---------------------------------------------------------------------------
#define XAh_ 0
#define XAl_ (XAh_ + 128 * 68)    // 8704
#define XBh_ (XAl_ + 128 * 68)    // 17408
#define XBl_ (XBh_ +  64 * 72)    // 22016
#define XBI_ (XBl_ +  64 * 72)    // 26624
#define XG_SMEM_BYTES ((XBI_ + 512) * 4)   // 108544

__global__ void __launch_bounds__(256, 2) xg_mma_kernel(const float* __restrict__ x,
                                                        const float* __restrict__ bih,
                                                        const float* __restrict__ bhh) {
    extern __shared__ float sm[];
    const int tid = threadIdx.x;
    const int lane = tid & 31;
    const int w = tid >> 5;
    const int mg = w & 3;
    const int nh2 = w >> 2;
    const size_t rowBase = (size_t)blockIdx.x * 128;

    const int rA = mg * 32 + (lane >> 2);
    const int kA = lane & 3;
    const int cB = lane >> 2;
    const int kB = lane & 3;

    for (int i = tid; i < 2048; i += 256) {
        int r = i >> 4, c4 = i & 15;
        float4 v = reinterpret_cast<const float4*>(x)[(rowBase + r) * 16 + c4];
        uint32_t h, l;
        float* dh = &sm[XAh_ + r * 68 + c4 * 4];
        float* dl = &sm[XAl_ + r * 68 + c4 * 4];
        tf32_split(v.x, h, l); dh[0] = __uint_as_float(h); dl[0] = __uint_as_float(l);
        tf32_split(v.y, h, l); dh[1] = __uint_as_float(h); dl[1] = __uint_as_float(l);
        tf32_split(v.z, h, l); dh[2] = __uint_as_float(h); dl[2] = __uint_as_float(l);
        tf32_split(v.w, h, l); dh[3] = __uint_as_float(h); dl[3] = __uint_as_float(l);
    }
    for (int i = tid; i < G4_; i += 256) sm[XBI_ + i] = bih[i] + bhh[i];

    for (int ch = 0; ch < 8; ch++) {
        __syncthreads();
        for (int i = tid; i < 1024; i += 256) {
            int k = i >> 4, n4 = i & 15;
            *reinterpret_cast<float4*>(&sm[XBh_ + k * 72 + n4 * 4]) =
                reinterpret_cast<const float4*>(g_Wxh)[k * 128 + ch * 16 + n4];
            *reinterpret_cast<float4*>(&sm[XBl_ + k * 72 + n4 * 4]) =
                reinterpret_cast<const float4*>(g_Wxl)[k * 128 + ch * 16 + n4];
        }
        __syncthreads();

        float acc[2][4][4];
#pragma unroll
        for (int mf = 0; mf < 2; mf++)
#pragma unroll
            for (int nt = 0; nt < 4; nt++)
#pragma unroll
                for (int q = 0; q < 4; q++) acc[mf][nt][q] = 0.f;

#pragma unroll
        for (int ks = 0; ks < 8; ks++) {
            uint32_t Ah[2][4], Al[2][4];
#pragma unroll
            for (int mf = 0; mf < 2; mf++) {
                int r = rA + mf * 16;
                int k = ks * 8 + kA;
                Ah[mf][0] = __float_as_uint(sm[XAh_ + r * 68 + k]);
                Ah[mf][1] = __float_as_uint(sm[XAh_ + (r + 8) * 68 + k]);
                Ah[mf][2] = __float_as_uint(sm[XAh_ + r * 68 + k + 4]);
                Ah[mf][3] = __float_as_uint(sm[XAh_ + (r + 8) * 68 + k + 4]);
                Al[mf][0] = __float_as_uint(sm[XAl_ + r * 68 + k]);
                Al[mf][1] = __float_as_uint(sm[XAl_ + (r + 8) * 68 + k]);
                Al[mf][2] = __float_as_uint(sm[XAl_ + r * 68 + k + 4]);
                Al[mf][3] = __float_as_uint(sm[XAl_ + (r + 8) * 68 + k + 4]);
            }
#pragma unroll
            for (int nt = 0; nt < 4; nt++) {
                int n = nh2 * 32 + nt * 8 + cB;
                int k = ks * 8 + kB;
                uint32_t Bh[2], Bl[2];
                Bh[0] = __float_as_uint(sm[XBh_ + k * 72 + n]);
                Bh[1] = __float_as_uint(sm[XBh_ + (k + 4) * 72 + n]);
                Bl[0] = __float_as_uint(sm[XBl_ + k * 72 + n]);
                Bl[1] = __float_as_uint(sm[XBl_ + (k + 4) * 72 + n]);
#pragma unroll
                for (int mf = 0; mf < 2; mf++) {
                    mma8(acc[mf][nt], Ah[mf], Bh);
                    mma8(acc[mf][nt], Al[mf], Bh);
                    mma8(acc[mf][nt], Ah[mf], Bl);
                }
            }
        }

#pragma unroll
        for (int mf = 0; mf < 2; mf++) {
            size_t r0 = rowBase + rA + mf * 16;
#pragma unroll
            for (int nt = 0; nt < 4; nt++) {
                int col = ch * 64 + nh2 * 32 + nt * 8 + (lane & 3) * 2;
                float bb0 = sm[XBI_ + col];
                float bb1 = sm[XBI_ + col + 1];
                float2 v0, v1;
                v0.x = acc[mf][nt][0] + bb0;
                v0.y = acc[mf][nt][1] + bb1;
                v1.x = acc[mf][nt][2] + bb0;
                v1.y = acc[mf][nt][3] + bb1;
                *reinterpret_cast<float2*>(&g_xg[r0 * G4_ + col]) = v0;
                *reinterpret_cast<float2*>(&g_xg[(r0 + 8) * G4_ + col]) = v1;
            }
        }
    }
}

// ---------------------------------------------------------------------------
// Kernel B: persistent LSTM scan — one-barrier structure at 256 threads.
// Thread tid -> u = tid>>1 (unit), b = tid&1 (batch row).  Each thread
// computes all 4 gates of unit u for ONE row -> thread-local cell update,
// sH double-buffered, ONE __syncthreads per step.
// Lane pairs (2i,2i+1) read the SAME weight rows -> LDS broadcast dedup:
// the 221 KB weight image crosses the crossbar exactly once per step.
// h loads: 2 distinct addresses per warp-LDS -> near-free.
// KS=108 (stride 27 f4, odd -> conflict-free), KR=20 (80 weight regs).
// ---------------------------------------------------------------------------
#define KS_ 108
#define KR_ 20
#define LSTM_SMEM_BYTES ((G4_ * KS_ + 2 * 2 * H_) * 4)   // 221184 + 2048 = 223232

__global__ void __launch_bounds__(256, 1) lstm_kernel(const float* __restrict__ Whh,
                                                      float* __restrict__ outp) {
    extern __shared__ float smem[];
    float* sW = smem;                 // [512 gate-rows][108]
    float* sH = sW + G4_ * KS_;       // 2 buffers x [2 rows][128]

    const int tid = threadIdx.x;
    const int u = tid >> 1;           // unit 0..127
    const int b = tid & 1;            // batch row within CTA
    const int row0 = blockIdx.x * 2;
    const int row = row0 + b;

    // stage W_hh k<108 (27 float4 per gate row; gmem row stride = 32 float4)
    const float4* W4 = reinterpret_cast<const float4*>(Whh);
    float4* sW4 = reinterpret_cast<float4*>(sW);
    for (int idx = tid; idx < G4_ * 27; idx += 256) {
        int g = idx / 27, k4 = idx % 27;
        sW4[g * 27 + k4] = W4[g * 32 + k4];
    }
    // register tail weights k = 108..127, 4 gate rows for this unit
    float rw[4][KR_];
#pragma unroll
    for (int g = 0; g < 4; g++)
#pragma unroll
        for (int j = 0; j < KR_; j++)
            rw[g][j] = Whh[(g * H_ + u) * H_ + KS_ + j];

    sH[tid] = 0.f;                    // buffer 0 = initial h (256 floats)
    float c = 0.f, hv = 0.f;
    __syncthreads();

    const float4* wp0 = sW4 + (0 * H_ + u) * 27;
    const float4* wp1 = sW4 + (1 * H_ + u) * 27;
    const float4* wp2 = sW4 + (2 * H_ + u) * 27;
    const float4* wp3 = sW4 + (3 * H_ + u) * 27;

    // prefetch xg for t=0 (4 gates of this row/unit)
    float xn[4];
    {
        size_t pb = (size_t)row * G4_;
#pragma unroll
        for (int g = 0; g < 4; g++) xn[g] = g_xg[pb + g * H_ + u];
    }

    for (int t = 0; t < T_; t++) {
        const int p = t & 1;
        const float4* hp = reinterpret_cast<const float4*>(sH + p * 2 * H_ + b * H_);

        float a0 = xn[0], a1 = xn[1], a2 = xn[2], a3 = xn[3];
        if (t + 1 < T_) {   // prefetch next timestep
            size_t nb = ((size_t)(t + 1) * B_ + row) * G4_;
#pragma unroll
            for (int g = 0; g < 4; g++) xn[g] = g_xg[nb + g * H_ + u];
        }

#pragma unroll 9
        for (int k4 = 0; k4 < 27; k4++) {
            float4 h = hp[k4];
            float4 w0 = wp0[k4], w1 = wp1[k4], w2 = wp2[k4], w3 = wp3[k4];
            a0 += w0.x*h.x + w0.y*h.y + w0.z*h.z + w0.w*h.w;
            a1 += w1.x*h.x + w1.y*h.y + w1.z*h.z + w1.w*h.w;
            a2 += w2.x*h.x + w2.y*h.y + w2.z*h.z + w2.w*h.w;
            a3 += w3.x*h.x + w3.y*h.y + w3.z*h.z + w3.w*h.w;
        }
#pragma unroll
        for (int j4 = 0; j4 < 5; j4++) {   // register tail k = 108..127
            float4 h = hp[27 + j4];
            a0 += rw[0][4*j4]*h.x + rw[0][4*j4+1]*h.y + rw[0][4*j4+2]*h.z + rw[0][4*j4+3]*h.w;
            a1 += rw[1][4*j4]*h.x + rw[1][4*j4+1]*h.y + rw[1][4*j4+2]*h.z + rw[1][4*j4+3]*h.w;
            a2 += rw[2][4*j4]*h.x + rw[2][4*j4+1]*h.y + rw[2][4*j4+2]*h.z + rw[2][4*j4+3]*h.w;
            a3 += rw[3][4*j4]*h.x + rw[3][4*j4+1]*h.y + rw[3][4*j4+2]*h.z + rw[3][4*j4+3]*h.w;
        }

        // thread-local LSTM cell update (PyTorch gate order i,f,g,o)
        float iv = sigf(a0), fv = sigf(a1);
        float gv = tanhfast(a2), ov = sigf(a3);
        c = fv * c + iv * gv;
        hv = ov * tanhfast(c);

        sH[(p ^ 1) * 2 * H_ + b * H_ + u] = hv;
        g_hs[((size_t)t * B_ + row) * H_ + u] = hv;
        __syncthreads();   // the ONLY per-step barrier
    }
    outp[HT_OFF + (size_t)row * H_ + u] = hv;
    outp[CT_OFF + (size_t)row * H_ + u] = c;
}

// ---------------------------------------------------------------------------
// Kernel C (mma): fused MLP — R10/R8 version (proven 2.05 ms), unchanged.
// ---------------------------------------------------------------------------
#define SA_    0
#define SB1H_  (SA_   + 128 * 132)       // 16896
#define SB1L_  (SB1H_ + 128 * 72)        // 26112
#define SHID_  (SB1L_ + 128 * 72)        // 35328
#define SW2H_  (SHID_ + 128 * 68)        // 44032
#define SW2L_  (SW2H_ +  64 * 72)        // 48640
#define SB1V_  (SW2L_ +  64 * 72)        // 53248
#define SB2V_  (SB1V_ + 512)             // 53760
#define MLP_SMEM_BYTES  ((SB2V_ + 64) * 4)   // 215296

__global__ void __launch_bounds__(256, 1) mlp_mma_kernel(const float* __restrict__ b1,
                                                         const float* __restrict__ b2,
                                                         float* __restrict__ outp) {
    extern __shared__ float sm[];
    const int tid = threadIdx.x;
    const int lane = tid & 31;
    const int w = tid >> 5;
    const int mg = w & 3;
    const int nh2 = w >> 2;
    const size_t rowBase = (size_t)blockIdx.x * 128;

    const int rA = mg * 32 + (lane >> 2);
    const int kA = lane & 3;
    const int cB = lane >> 2;
    const int kB = lane & 3;

    for (int i = tid; i < 4096; i += 256) {
        int r = i >> 5, c4 = i & 31;
        float4 v = reinterpret_cast<const float4*>(g_hs)[(rowBase + r) * 32 + c4];
        *reinterpret_cast<float4*>(&sm[SA_ + r * 132 + c4 * 4]) = v;
    }
    for (int i = tid; i < NH_; i += 256) sm[SB1V_ + i] = b1[i];
    if (tid < O_) sm[SB2V_ + tid] = b2[tid];

    float accO[2][4][4];
#pragma unroll
    for (int mf = 0; mf < 2; mf++)
#pragma unroll
        for (int nt = 0; nt < 4; nt++)
#pragma unroll
            for (int q = 0; q < 4; q++) accO[mf][nt][q] = 0.f;

    for (int c = 0; c < 8; c++) {
        __syncthreads();
        for (int i = tid; i < 2048; i += 256) {
            int k = i >> 4, n4 = i & 15;
            *reinterpret_cast<float4*>(&sm[SB1H_ + k * 72 + n4 * 4]) =
                reinterpret_cast<const float4*>(g_W1h)[k * 128 + c * 16 + n4];
            *reinterpret_cast<float4*>(&sm[SB1L_ + k * 72 + n4 * 4]) =
                reinterpret_cast<const float4*>(g_W1l)[k * 128 + c * 16 + n4];
        }
        for (int i = tid; i < 1024; i += 256) {
            int k = i >> 4, n4 = i & 15;
            *reinterpret_cast<float4*>(&sm[SW2H_ + k * 72 + n4 * 4]) =
                reinterpret_cast<const float4*>(g_W2h)[(c * 64 + k) * 16 + n4];
            *reinterpret_cast<float4*>(&sm[SW2L_ + k * 72 + n4 * 4]) =
                reinterpret_cast<const float4*>(g_W2l)[(c * 64 + k) * 16 + n4];
        }
        __syncthreads();

        float acc[2][4][4];
#pragma unroll
        for (int mf = 0; mf < 2; mf++)
#pragma unroll
            for (int nt = 0; nt < 4; nt++)
#pragma unroll
                for (int q = 0; q < 4; q++) acc[mf][nt][q] = 0.f;

#pragma unroll 2
        for (int ks = 0; ks < 16; ks++) {
            uint32_t Ah[2][4], Al[2][4];
#pragma unroll
            for (int mf = 0; mf < 2; mf++) {
                int r = rA + mf * 16;
                int k = ks * 8 + kA;
                float a0 = sm[SA_ + r * 132 + k];
                float a1 = sm[SA_ + (r + 8) * 132 + k];
                float a2 = sm[SA_ + r * 132 + k + 4];
                float a3 = sm[SA_ + (r + 8) * 132 + k + 4];
                tf32_split(a0, Ah[mf][0], Al[mf][0]);
                tf32_split(a1, Ah[mf][1], Al[mf][1]);
                tf32_split(a2, Ah[mf][2], Al[mf][2]);
                tf32_split(a3, Ah[mf][3], Al[mf][3]);
            }
#pragma unroll
            for (int nt = 0; nt < 4; nt++) {
                int n = nh2 * 32 + nt * 8 + cB;
                int k = ks * 8 + kB;
                uint32_t Bh[2], Bl[2];
                Bh[0] = __float_as_uint(sm[SB1H_ + k * 72 + n]);
                Bh[1] = __float_as_uint(sm[SB1H_ + (k + 4) * 72 + n]);
                Bl[0] = __float_as_uint(sm[SB1L_ + k * 72 + n]);
                Bl[1] = __float_as_uint(sm[SB1L_ + (k + 4) * 72 + n]);
#pragma unroll
                for (int mf = 0; mf < 2; mf++) {
                    mma8(acc[mf][nt], Ah[mf], Bh);
                    mma8(acc[mf][nt], Ah[mf], Bl);
                    mma8(acc[mf][nt], Al[mf], Bh);
                }
            }
        }

#pragma unroll
        for (int mf = 0; mf < 2; mf++)
#pragma unroll
            for (int nt = 0; nt < 4; nt++) {
                int r = rA + mf * 16;
                int col = nh2 * 32 + nt * 8 + (lane & 3) * 2;
                float bb0 = sm[SB1V_ + c * 64 + col];
                float bb1 = sm[SB1V_ + c * 64 + col + 1];
                float2 v0, v1;
                v0.x = fmaxf(acc[mf][nt][0] + bb0, 0.f);
                v0.y = fmaxf(acc[mf][nt][1] + bb1, 0.f);
                v1.x = fmaxf(acc[mf][nt][2] + bb0, 0.f);
                v1.y = fmaxf(acc[mf][nt][3] + bb1, 0.f);
                *reinterpret_cast<float2*>(&sm[SHID_ + r * 68 + col]) = v0;
                *reinterpret_cast<float2*>(&sm[SHID_ + (r + 8) * 68 + col]) = v1;
            }
        __syncthreads();

#pragma unroll 2
        for (int ks = 0; ks < 8; ks++) {
            uint32_t Ah[2][4], Al[2][4];
#pragma unroll
            for (int mf = 0; mf < 2; mf++) {
                int r = rA + mf * 16;
                int k = ks * 8 + kA;
                float a0 = sm[SHID_ + r * 68 + k];
                float a1 = sm[SHID_ + (r + 8) * 68 + k];
                float a2 = sm[SHID_ + r * 68 + k + 4];
                float a3 = sm[SHID_ + (r + 8) * 68 + k + 4];
                tf32_split(a0, Ah[mf][0], Al[mf][0]);
                tf32_split(a1, Ah[mf][1], Al[mf][1]);
                tf32_split(a2, Ah[mf][2], Al[mf][2]);
                tf32_split(a3, Ah[mf][3], Al[mf][3]);
            }
#pragma unroll
            for (int nt = 0; nt < 4; nt++) {
                int n = nh2 * 32 + nt * 8 + cB;
                int k = ks * 8 + kB;
                uint32_t Bh[2], Bl[2];
                Bh[0] = __float_as_uint(sm[SW2H_ + k * 72 + n]);
                Bh[1] = __float_as_uint(sm[SW2H_ + (k + 4) * 72 + n]);
                Bl[0] = __float_as_uint(sm[SW2L_ + k * 72 + n]);
                Bl[1] = __float_as_uint(sm[SW2L_ + (k + 4) * 72 + n]);
#pragma unroll
                for (int mf = 0; mf < 2; mf++) {
                    mma8(accO[mf][nt], Ah[mf], Bh);
                    mma8(accO[mf][nt], Ah[mf], Bl);
                    mma8(accO[mf][nt], Al[mf], Bh);
                }
            }
        }
    }

#pragma unroll
    for (int mf = 0; mf < 2; mf++) {
        size_t r0 = rowBase + rA + mf * 16;
#pragma unroll
        for (int nt = 0; nt < 4; nt++) {
            int col = nh2 * 32 + nt * 8 + (lane & 3) * 2;
            float bo0 = sm[SB2V_ + col];
            float bo1 = sm[SB2V_ + col + 1];
            float2 v0, v1;
            v0.x = accO[mf][nt][0] + bo0;
            v0.y = accO[mf][nt][1] + bo1;
            v1.x = accO[mf][nt][2] + bo0;
            v1.y = accO[mf][nt][3] + bo1;
            *reinterpret_cast<float2*>(outp + r0 * O_ + col) = v0;
            *reinterpret_cast<float2*>(outp + (r0 + 8) * O_ + col) = v1;
        }
    }
}

// ---------------------------------------------------------------------------
// Launcher
// ---------------------------------------------------------------------------
extern "C" void kernel_launch(void* const* d_in, const int* in_sizes, int n_in,
                              void* d_out, int out_size) {
    const float* x    = (const float*)d_in[0];
    const float* Wih  = (const float*)d_in[1];
    const float* Whh  = (const float*)d_in[2];
    const float* bih  = (const float*)d_in[3];
    const float* bhh  = (const float*)d_in[4];
    const float* W1   = (const float*)d_in[5];
    const float* b1   = (const float*)d_in[6];
    const float* W2   = (const float*)d_in[7];
    const float* b2   = (const float*)d_in[8];
    float* out = (float*)d_out;

    cudaFuncSetAttribute(xg_mma_kernel,  cudaFuncAttributeMaxDynamicSharedMemorySize, XG_SMEM_BYTES);
    cudaFuncSetAttribute(lstm_kernel,    cudaFuncAttributeMaxDynamicSharedMemorySize, LSTM_SMEM_BYTES);
    cudaFuncSetAttribute(mlp_mma_kernel, cudaFuncAttributeMaxDynamicSharedMemorySize, MLP_SMEM_BYTES);

    prep_kernel<<<64, 256>>>(Wih, W1, W2);
    xg_mma_kernel<<<(T_ * B_) / 128, 256, XG_SMEM_BYTES>>>(x, bih, bhh);
    lstm_kernel<<<B_ / 2, 256, LSTM_SMEM_BYTES>>>(Whh, out);
    mlp_mma_kernel<<<(T_ * B_) / 128, 256, MLP_SMEM_BYTES>>>(b1, b2, out);
}